// round 11
// baseline (speedup 1.0000x reference)
#include <cuda_runtime.h>
#include <cuda_bf16.h>
#include <cuda_fp16.h>
#include <math.h>
#include <stdint.h>

#define N_NODES 50000
#define N_EDGES 800000
#define HIDDEN  256
#define HEADS   4
#define HEAD_DIM 64
#define LAYERS  3
#define NUM_GRAPHS 64
#define NEG_SLOPE 0.2f
#define SCAN_BLOCKS ((N_NODES + 1023) / 1024)   // 49

// ---------------- scratch (device globals; no allocation allowed) ----------------
__device__ float  g_h   [(long long)N_NODES * HIDDEN];
__device__ float  g_hp  [(long long)N_NODES * HIDDEN];
__device__ __half g_hph [(long long)N_NODES * HIDDEN];   // fp16 copy of g_hp for gathers
__device__ float  g_ss  [N_NODES * HEADS];
__device__ float  g_sd  [N_NODES * HEADS];
__device__ float  g_c   [HEADS * 3];
__device__ float  g_pool[NUM_GRAPHS * HIDDEN];
__device__ float  g_cnt [NUM_GRAPHS];
// CSR scratch
__device__ int    g_deg[N_NODES];
__device__ int    g_off[N_NODES + 1];
__device__ int    g_cur[N_NODES];
__device__ int    g_bsum[SCAN_BLOCKS];
__device__ int    g_csr_src[N_EDGES];
__device__ float4 g_csr_att[N_EDGES];

// ---------------- helpers ----------------
__device__ __forceinline__ float elu1(float v) {
    return v > 0.f ? v : expm1f(v);
}

__device__ __forceinline__ uint32_t f2tf32(float x) {
    uint32_t u;
    asm("cvt.rna.tf32.f32 %0, %1;" : "=r"(u) : "f"(x));
    return u;
}

// ---------------- init: pooling accumulators + degree histogram ----------------
__global__ void init_kernel() {
    int i = blockIdx.x * blockDim.x + threadIdx.x;
    if (i < NUM_GRAPHS * HIDDEN) g_pool[i] = 0.f;
    if (i < NUM_GRAPHS) g_cnt[i] = 0.f;
    if (i < N_NODES) g_deg[i] = 0;
}

// ---------------- block LN reduce helper (256 threads) ----------------
__device__ __forceinline__ float block_sum_256(float v, float* ws) {
    int lane = threadIdx.x & 31, wid = threadIdx.x >> 5;
    #pragma unroll
    for (int o = 16; o > 0; o >>= 1) v += __shfl_xor_sync(0xFFFFFFFFu, v, o);
    if (lane == 0) ws[wid] = v;
    __syncthreads();
    float s = ws[0] + ws[1] + ws[2] + ws[3] + ws[4] + ws[5] + ws[6] + ws[7];
    __syncthreads();
    return s;
}

// ---------------- input projection + LN + ELU ----------------
__global__ void input_proj_kernel(const float* __restrict__ x,
                                  const float* __restrict__ Win,
                                  const float* __restrict__ bin,
                                  const float* __restrict__ lg,
                                  const float* __restrict__ lb) {
    int n = blockIdx.x;
    int j = threadIdx.x;
    __shared__ float xs[8];
    __shared__ float ws[8];
    if (j < 8) xs[j] = x[n * 8 + j];
    __syncthreads();
    float y = bin[j];
    #pragma unroll
    for (int k = 0; k < 8; k++) y += xs[k] * Win[k * HIDDEN + j];
    float mu = block_sum_256(y, ws) * (1.f / HIDDEN);
    float d = y - mu;
    float var = block_sum_256(d * d, ws) * (1.f / HIDDEN);
    float v = d * rsqrtf(var + 1e-5f) * lg[j] + lb[j];
    g_h[(long long)n * HIDDEN + j] = elu1(v);
}

// ---------------- CSR build ----------------
__global__ void hist_kernel(const int* __restrict__ ei) {
    int e = blockIdx.x * blockDim.x + threadIdx.x;
    if (e >= N_EDGES) return;
    atomicAdd(&g_deg[ei[N_EDGES + e]], 1);
}

// phase 1: per-block (1024-elem chunk) totals
__global__ void scan_reduce_kernel() {
    __shared__ int ws[8];
    int b = blockIdx.x;
    int t = threadIdx.x;             // 256 threads
    int base = b * 1024;
    int s = 0;
    #pragma unroll
    for (int i = 0; i < 4; i++) {
        int idx = base + t + i * 256;
        if (idx < N_NODES) s += g_deg[idx];
    }
    int lane = t & 31, wid = t >> 5;
    #pragma unroll
    for (int o = 16; o > 0; o >>= 1) s += __shfl_xor_sync(0xFFFFFFFFu, s, o);
    if (lane == 0) ws[wid] = s;
    __syncthreads();
    if (t == 0) g_bsum[b] = ws[0] + ws[1] + ws[2] + ws[3] + ws[4] + ws[5] + ws[6] + ws[7];
}

// phase 2: block-local exclusive scan + inline top-level scan of 49 block sums
__global__ void scan_final_kernel() {
    __shared__ int wtot[32];
    __shared__ int bex[SCAN_BLOCKS];
    int b = blockIdx.x;
    int t = threadIdx.x;             // 1024 threads
    int lane = t & 31, wid = t >> 5;

    if (wid == 0) {
        int v = (lane < SCAN_BLOCKS) ? g_bsum[lane] : 0;
        int incl = v;
        #pragma unroll
        for (int o = 1; o < 32; o <<= 1) {
            int y = __shfl_up_sync(0xFFFFFFFFu, incl, o);
            if (lane >= o) incl += y;
        }
        if (lane < SCAN_BLOCKS) bex[lane] = incl - v;
        int tot = __shfl_sync(0xFFFFFFFFu, incl, 31);
        int v2 = (lane + 32 < SCAN_BLOCKS) ? g_bsum[lane + 32] : 0;
        int incl2 = v2;
        #pragma unroll
        for (int o = 1; o < 32; o <<= 1) {
            int y = __shfl_up_sync(0xFFFFFFFFu, incl2, o);
            if (lane >= o) incl2 += y;
        }
        if (lane + 32 < SCAN_BLOCKS) bex[lane + 32] = tot + incl2 - v2;
    }

    int i = b * 1024 + t;
    int v = (i < N_NODES) ? g_deg[i] : 0;
    int incl = v;
    #pragma unroll
    for (int o = 1; o < 32; o <<= 1) {
        int y = __shfl_up_sync(0xFFFFFFFFu, incl, o);
        if (lane >= o) incl += y;
    }
    if (lane == 31) wtot[wid] = incl;
    __syncthreads();
    if (wid == 0) {
        int w = wtot[lane];
        #pragma unroll
        for (int o = 1; o < 32; o <<= 1) {
            int y = __shfl_up_sync(0xFFFFFFFFu, w, o);
            if (lane >= o) w += y;
        }
        wtot[lane] = w;
    }
    __syncthreads();
    int ex = incl - v + (wid > 0 ? wtot[wid - 1] : 0) + bex[b];
    if (i < N_NODES) {
        g_off[i] = ex;
        g_cur[i] = ex;
    }
    if (b == 0 && t == 0) g_off[N_NODES] = N_EDGES;
}

__global__ void scatter_kernel(const int* __restrict__ ei,
                               const float* __restrict__ ea) {
    int e = blockIdx.x * blockDim.x + threadIdx.x;
    if (e >= N_EDGES) return;
    int s = ei[e];
    int d = ei[N_EDGES + e];
    int pos = atomicAdd(&g_cur[d], 1);
    g_csr_src[pos] = s;
    g_csr_att[pos] = make_float4(ea[e * 3 + 0], ea[e * 3 + 1], ea[e * 3 + 2], 0.f);
}

// ---------------- mma.sync tf32 GEMM: C[M,256] = A[M,256] @ B[256,256] + bias ----------------
#define GBM 128
#define GBN 128
#define GBK 32
#define A_STRIDE 36
#define B_STRIDE 136
#define ASZ (GBM * A_STRIDE)
#define BSZ (GBK * B_STRIDE)
#define GEMM_DSMEM (2 * (ASZ + BSZ) * 4)

__global__ void __launch_bounds__(256, 2)
gemm_mma_kernel(const float* __restrict__ A,
                const float* __restrict__ B,
                const float* __restrict__ bias,
                float* __restrict__ C,
                int M) {
    extern __shared__ uint32_t sm[];
    uint32_t* As = sm;               // [2][ASZ]
    uint32_t* Bs = sm + 2 * ASZ;     // [2][BSZ]

    int tid = threadIdx.x;
    int warp = tid >> 5;
    int lane = tid & 31;
    int wm = warp >> 2;
    int wn = warp & 3;
    int cCol = blockIdx.x;
    int cRow = blockIdx.y;

    int arow_base = tid >> 3;            // 0..31
    int acol4 = (tid & 7) * 4;           // 0..28
    int bk = tid >> 5;                   // 0..7
    int bn4 = (tid & 31) * 4;            // 0..124
    const float* Bb = B + cCol * GBN;

    float acc[4][4][4];
    #pragma unroll
    for (int i = 0; i < 4; i++)
        #pragma unroll
        for (int j = 0; j < 4; j++)
            #pragma unroll
            for (int r = 0; r < 4; r++) acc[i][j][r] = 0.f;

    int lr = lane >> 2;
    int lc = lane & 3;

    float4 ar[4], br[4];
    #pragma unroll
    for (int i = 0; i < 4; i++) {
        int grow = cRow * GBM + arow_base + i * 32;
        ar[i] = (grow < M) ? *(const float4*)&A[(long long)grow * 256 + acol4]
                           : make_float4(0.f, 0.f, 0.f, 0.f);
        br[i] = *(const float4*)&Bb[(long long)(bk + i * 8) * 256 + bn4];
    }
    #pragma unroll
    for (int i = 0; i < 4; i++) {
        *(uint4*)&As[(arow_base + i * 32) * A_STRIDE + acol4] =
            make_uint4(f2tf32(ar[i].x), f2tf32(ar[i].y), f2tf32(ar[i].z), f2tf32(ar[i].w));
        *(uint4*)&Bs[(bk + i * 8) * B_STRIDE + bn4] =
            make_uint4(f2tf32(br[i].x), f2tf32(br[i].y), f2tf32(br[i].z), f2tf32(br[i].w));
    }
    __syncthreads();

    for (int kc = 0; kc < 256 / GBK; kc++) {
        int st = kc & 1;
        int nst = st ^ 1;
        if (kc < 7) {
            int kb = (kc + 1) * GBK;
            #pragma unroll
            for (int i = 0; i < 4; i++) {
                int grow = cRow * GBM + arow_base + i * 32;
                ar[i] = (grow < M) ? *(const float4*)&A[(long long)grow * 256 + kb + acol4]
                                   : make_float4(0.f, 0.f, 0.f, 0.f);
                br[i] = *(const float4*)&Bb[(long long)(kb + bk + i * 8) * 256 + bn4];
            }
        }

        const uint32_t* Asb = As + st * ASZ;
        const uint32_t* Bsb = Bs + st * BSZ;
        #pragma unroll
        for (int ks = 0; ks < GBK / 8; ks++) {
            int k0 = ks * 8;
            uint32_t bf[4][2];
            #pragma unroll
            for (int nt = 0; nt < 4; nt++) {
                int nb = wn * 32 + nt * 8 + lr;
                bf[nt][0] = Bsb[(k0 + lc) * B_STRIDE + nb];
                bf[nt][1] = Bsb[(k0 + lc + 4) * B_STRIDE + nb];
            }
            #pragma unroll
            for (int mt = 0; mt < 4; mt++) {
                int rm = wm * 64 + mt * 16;
                uint32_t a0 = Asb[(rm + lr) * A_STRIDE + k0 + lc];
                uint32_t a1 = Asb[(rm + lr + 8) * A_STRIDE + k0 + lc];
                uint32_t a2 = Asb[(rm + lr) * A_STRIDE + k0 + lc + 4];
                uint32_t a3 = Asb[(rm + lr + 8) * A_STRIDE + k0 + lc + 4];
                #pragma unroll
                for (int nt = 0; nt < 4; nt++) {
                    asm volatile(
                        "mma.sync.aligned.m16n8k8.row.col.f32.tf32.tf32.f32 "
                        "{%0,%1,%2,%3}, {%4,%5,%6,%7}, {%8,%9}, {%0,%1,%2,%3};"
                        : "+f"(acc[mt][nt][0]), "+f"(acc[mt][nt][1]),
                          "+f"(acc[mt][nt][2]), "+f"(acc[mt][nt][3])
                        : "r"(a0), "r"(a1), "r"(a2), "r"(a3),
                          "r"(bf[nt][0]), "r"(bf[nt][1]));
                }
            }
        }
        if (kc < 7) {
            uint32_t* Asn = As + nst * ASZ;
            uint32_t* Bsn = Bs + nst * BSZ;
            #pragma unroll
            for (int i = 0; i < 4; i++) {
                *(uint4*)&Asn[(arow_base + i * 32) * A_STRIDE + acol4] =
                    make_uint4(f2tf32(ar[i].x), f2tf32(ar[i].y), f2tf32(ar[i].z), f2tf32(ar[i].w));
                *(uint4*)&Bsn[(bk + i * 8) * B_STRIDE + bn4] =
                    make_uint4(f2tf32(br[i].x), f2tf32(br[i].y), f2tf32(br[i].z), f2tf32(br[i].w));
            }
        }
        __syncthreads();
    }

    // epilogue: f32 C (+bias) and fp16 copy for the gather path
    #pragma unroll
    for (int mt = 0; mt < 4; mt++) {
        int row0 = cRow * GBM + wm * 64 + mt * 16 + lr;
        #pragma unroll
        for (int nt = 0; nt < 4; nt++) {
            int col = cCol * GBN + wn * 32 + nt * 8 + lc * 2;
            float b0 = bias[col], b1 = bias[col + 1];
            if (row0 < M) {
                float2 v0 = make_float2(acc[mt][nt][0] + b0, acc[mt][nt][1] + b1);
                *(float2*)&C[(long long)row0 * 256 + col] = v0;
                *(__half2*)&g_hph[(long long)row0 * 256 + col] = __floats2half2_rn(v0.x, v0.y);
            }
            if (row0 + 8 < M) {
                float2 v1 = make_float2(acc[mt][nt][2] + b0, acc[mt][nt][3] + b1);
                *(float2*)&C[(long long)(row0 + 8) * 256 + col] = v1;
                *(__half2*)&g_hph[(long long)(row0 + 8) * 256 + col] = __floats2half2_rn(v1.x, v1.y);
            }
        }
    }
}

// ---------------- node attention scores (fp16 input; + per-layer c precompute) ----------------
__global__ void node_score_kernel(const float* __restrict__ as_,
                                  const float* __restrict__ ad_,
                                  const float* __restrict__ We,
                                  const float* __restrict__ ae) {
    if (blockIdx.x == 0 && threadIdx.x < HEADS * 3) {
        int i = threadIdx.x;
        int hh = i / 3, k = i % 3;
        float s = 0.f;
        for (int d = 0; d < HEAD_DIM; d++)
            s += We[k * HIDDEN + hh * HEAD_DIM + d] * ae[hh * HEAD_DIM + d];
        g_c[i] = s;
    }
    int gw = (blockIdx.x * blockDim.x + threadIdx.x) >> 5;
    int lane = threadIdx.x & 31;
    if (gw >= N_NODES * HEADS) return;
    int n = gw >> 2, hh = gw & 3;
    const __half* row = g_hph + (long long)n * HIDDEN + hh * HEAD_DIM;
    float v0 = __half2float(row[lane]), v1 = __half2float(row[lane + 32]);
    float s = v0 * as_[hh * HEAD_DIM + lane] + v1 * as_[hh * HEAD_DIM + lane + 32];
    float t = v0 * ad_[hh * HEAD_DIM + lane] + v1 * ad_[hh * HEAD_DIM + lane + 32];
    #pragma unroll
    for (int o = 16; o > 0; o >>= 1) {
        s += __shfl_xor_sync(0xFFFFFFFFu, s, o);
        t += __shfl_xor_sync(0xFFFFFFFFu, t, o);
    }
    if (lane == 0) {
        g_ss[gw] = s;
        g_sd[gw] = t;
    }
}

// ---------------- fused GAT layer: single-pass online softmax + agg + residual + ELU ----
// one warp per dst node; lane owns 8 columns (head h = lane>>3)
__global__ void gat_fused_kernel() {
    int gw = (blockIdx.x * blockDim.x + threadIdx.x) >> 5;
    int lane = threadIdx.x & 31;
    if (gw >= N_NODES) return;
    int n = gw;
    int r0 = g_off[n], r1 = g_off[n + 1];
    int h = lane >> 3;
    long long hb = (long long)n * HIDDEN + lane * 8;
    float4 hv0 = *(const float4*)&g_h[hb];
    float4 hv1 = *(const float4*)&g_h[hb + 4];

    if (r0 == r1) {
        hv0.x = elu1(hv0.x); hv0.y = elu1(hv0.y); hv0.z = elu1(hv0.z); hv0.w = elu1(hv0.w);
        hv1.x = elu1(hv1.x); hv1.y = elu1(hv1.y); hv1.z = elu1(hv1.z); hv1.w = elu1(hv1.w);
        *(float4*)&g_h[hb] = hv0;
        *(float4*)&g_h[hb + 4] = hv1;
        return;
    }

    float sdh = g_sd[n * 4 + h];
    float ch0 = g_c[h * 3 + 0], ch1 = g_c[h * 3 + 1], ch2 = g_c[h * 3 + 2];

    float m = -INFINITY, den = 0.f;
    float4 a0 = make_float4(0.f, 0.f, 0.f, 0.f);
    float4 a1 = make_float4(0.f, 0.f, 0.f, 0.f);

    for (int i = r0; i < r1; i++) {
        int s = g_csr_src[i];
        float4 at = g_csr_att[i];
        float l = g_ss[s * 4 + h] + sdh + at.x * ch0 + at.y * ch1 + at.z * ch2;
        l = l > 0.f ? l : NEG_SLOPE * l;
        float mn = fmaxf(m, l);
        float sc = expf(m - mn);     // 0 on first edge (m=-inf), 1 when max unchanged
        float w = expf(l - mn);
        m = mn;
        den = den * sc + w;
        uint4 u = *(const uint4*)&g_hph[(long long)s * HIDDEN + lane * 8];
        float2 f0 = __half22float2(*(__half2*)&u.x);
        float2 f1 = __half22float2(*(__half2*)&u.y);
        float2 f2 = __half22float2(*(__half2*)&u.z);
        float2 f3 = __half22float2(*(__half2*)&u.w);
        a0.x = a0.x * sc + w * f0.x; a0.y = a0.y * sc + w * f0.y;
        a0.z = a0.z * sc + w * f1.x; a0.w = a0.w * sc + w * f1.y;
        a1.x = a1.x * sc + w * f2.x; a1.y = a1.y * sc + w * f2.y;
        a1.z = a1.z * sc + w * f3.x; a1.w = a1.w * sc + w * f3.y;
    }
    float inv = 1.f / fmaxf(den, 1e-16f);
    hv0.x = elu1(a0.x * inv + hv0.x); hv0.y = elu1(a0.y * inv + hv0.y);
    hv0.z = elu1(a0.z * inv + hv0.z); hv0.w = elu1(a0.w * inv + hv0.w);
    hv1.x = elu1(a1.x * inv + hv1.x); hv1.y = elu1(a1.y * inv + hv1.y);
    hv1.z = elu1(a1.z * inv + hv1.z); hv1.w = elu1(a1.w * inv + hv1.w);
    *(float4*)&g_h[hb] = hv0;
    *(float4*)&g_h[hb + 4] = hv1;
}

// ---------------- output LN + ELU + write node_emb + pool ----------------
__global__ void ln_out_kernel(const float* __restrict__ lg,
                              const float* __restrict__ lb,
                              const int* __restrict__ batch,
                              float* __restrict__ node_out) {
    int n = blockIdx.x;
    int j = threadIdx.x;
    __shared__ float ws[8];
    float y = g_hp[(long long)n * HIDDEN + j];
    float mu = block_sum_256(y, ws) * (1.f / HIDDEN);
    float d = y - mu;
    float var = block_sum_256(d * d, ws) * (1.f / HIDDEN);
    float v = elu1(d * rsqrtf(var + 1e-5f) * lg[j] + lb[j]);
    node_out[(long long)n * HIDDEN + j] = v;
    int b = batch[n];
    atomicAdd(&g_pool[b * HIDDEN + j], v);
    if (j == 0) atomicAdd(&g_cnt[b], 1.0f);
}

// ---------------- graph mean pool output ----------------
__global__ void graph_out_kernel(float* __restrict__ out) {
    int i = blockIdx.x * blockDim.x + threadIdx.x;
    if (i < NUM_GRAPHS * HIDDEN) out[i] = g_pool[i] / fmaxf(g_cnt[i >> 8], 1.0f);
}

// ---------------- launch ----------------
extern "C" void kernel_launch(void* const* d_in, const int* in_sizes, int n_in,
                              void* d_out, int out_size) {
    const float* x          = (const float*)d_in[0];
    const int*   edge_index = (const int*)d_in[1];
    const float* edge_attr  = (const float*)d_in[2];
    const int*   batch      = (const int*)d_in[3];
    const float* W_in       = (const float*)d_in[4];
    const float* b_in       = (const float*)d_in[5];
    const float* ln_in_g    = (const float*)d_in[6];
    const float* ln_in_b    = (const float*)d_in[7];
    const float* W_gat      = (const float*)d_in[8];
    const float* b_gat      = (const float*)d_in[9];
    const float* W_e        = (const float*)d_in[10];
    const float* a_src      = (const float*)d_in[11];
    const float* a_dst      = (const float*)d_in[12];
    const float* a_edge     = (const float*)d_in[13];
    const float* W_out      = (const float*)d_in[14];
    const float* b_out      = (const float*)d_in[15];
    const float* ln_out_g   = (const float*)d_in[16];
    const float* ln_out_b   = (const float*)d_in[17];

    float* out = (float*)d_out;

    float *hp_, *h_;
    cudaGetSymbolAddress((void**)&h_, g_h);
    cudaGetSymbolAddress((void**)&hp_, g_hp);

    long long node_off = (long long)out_size - (long long)N_NODES * HIDDEN;
    float* node_out = (node_off >= 0) ? out + node_off : hp_;

    static int smem_set = 0;
    if (!smem_set) {
        cudaFuncSetAttribute(gemm_mma_kernel, cudaFuncAttributeMaxDynamicSharedMemorySize,
                             GEMM_DSMEM);
        smem_set = 1;
    }

    init_kernel<<<(N_NODES + 255) / 256, 256>>>();
    input_proj_kernel<<<N_NODES, HIDDEN>>>(x, W_in, b_in, ln_in_g, ln_in_b);
    hist_kernel<<<(N_EDGES + 255) / 256, 256>>>(edge_index);
    scan_reduce_kernel<<<SCAN_BLOCKS, 256>>>();
    scan_final_kernel<<<SCAN_BLOCKS, 1024>>>();
    scatter_kernel<<<(N_EDGES + 255) / 256, 256>>>(edge_index, edge_attr);

    dim3 gemm_grid(2, (N_NODES + GBM - 1) / GBM);
    int score_blocks = (N_NODES * HEADS * 32 + 255) / 256;
    int gat_blocks = (N_NODES * 32 + 255) / 256;

    for (int l = 0; l < LAYERS; l++) {
        const float* Wl  = W_gat + (long long)l * HIDDEN * HIDDEN;
        const float* bl  = b_gat + l * HIDDEN;
        const float* Wel = W_e + l * 3 * HIDDEN;
        const float* asl = a_src + l * HEADS * HEAD_DIM;
        const float* adl = a_dst + l * HEADS * HEAD_DIM;
        const float* ael = a_edge + l * HEADS * HEAD_DIM;

        gemm_mma_kernel<<<gemm_grid, 256, GEMM_DSMEM>>>(h_, Wl, bl, hp_, N_NODES);
        node_score_kernel<<<score_blocks, 256>>>(asl, adl, Wel, ael);
        gat_fused_kernel<<<gat_blocks, 256>>>();
    }

    gemm_mma_kernel<<<gemm_grid, 256, GEMM_DSMEM>>>(h_, W_out, b_out, hp_, N_NODES);
    ln_out_kernel<<<N_NODES, HIDDEN>>>(ln_out_g, ln_out_b, batch, node_out);
    graph_out_kernel<<<(NUM_GRAPHS * HIDDEN + 255) / 256, 256>>>(out);
}